// round 1
// baseline (speedup 1.0000x reference)
#include <cuda_runtime.h>
#include <cstdint>

// Problem constants (from reference)
#define NMAX 50000
#define EMAX 800000
#define FIN  128
#define FH   128
#define FOUT 64

// Scratch (static device globals — allocation-free per harness rules)
__device__ float g_deg[NMAX];
__device__ float g_isd[NMAX];           // deg^-1/2
__device__ float g_idg[NMAX];           // deg^-1
__device__ float g_h1[(size_t)NMAX * FH];
__device__ float g_agg1[(size_t)NMAX * FH];
__device__ float g_h2[(size_t)NMAX * FOUT];

// ---------------------------------------------------------------------------
// Degree pipeline
// ---------------------------------------------------------------------------
__global__ void k_init_deg(int n) {
    int i = blockIdx.x * blockDim.x + threadIdx.x;
    if (i < n) g_deg[i] = 1.0f;   // +1 self-loop
}

__global__ void k_edge_deg(const int* __restrict__ dst, int e) {
    int i = blockIdx.x * blockDim.x + threadIdx.x;
    if (i < e) atomicAdd(&g_deg[dst[i]], 1.0f);
}

__global__ void k_finalize_deg(int n) {
    int i = blockIdx.x * blockDim.x + threadIdx.x;
    if (i < n) {
        float d = g_deg[i];
        g_isd[i] = rsqrtf(d);
        g_idg[i] = 1.0f / d;
    }
}

// ---------------------------------------------------------------------------
// SGEMM with fused epilogue:
//   Hout[r,c] = (reluA ? relu(A) : A)[r,:] @ W[:,c]
//   Agg [r,c] = Hout[r,c] * idg[r] + bias[c]
// A is [N, 128] row-major, W is [128, F] row-major. F in {128, 64}.
// BM=BN=64, BK=16, 256 threads, 4x4 register tile.
// ---------------------------------------------------------------------------
template <int F, bool RELU_A>
__global__ void __launch_bounds__(256)
k_gemm_epi(const float* __restrict__ A, const float* __restrict__ W,
           const float* __restrict__ bias,
           float* __restrict__ Hout, float* __restrict__ Agg, int N) {
    constexpr int K = 128, BM = 64, BN = 64, BK = 16, TM = 4, TN = 4;
    __shared__ float As[BK][BM];
    __shared__ float Ws[BK][BN];

    const int tid = threadIdx.x;
    const int rowBase = blockIdx.y * BM;
    const int colBase = blockIdx.x * BN;
    const int ty = tid >> 4;        // 0..15
    const int tx = tid & 15;        // 0..15

    // A-tile load mapping: thread -> (row am, k-quad ak)
    const int am = tid >> 2;        // 0..63
    const int ak = (tid & 3) * 4;   // 0,4,8,12
    // W-tile load mapping: thread -> (k row wk, col-quad wn)
    const int wk = tid >> 4;        // 0..15
    const int wn = (tid & 15) * 4;  // 0..60

    float acc[TM][TN];
#pragma unroll
    for (int i = 0; i < TM; i++)
#pragma unroll
        for (int j = 0; j < TN; j++) acc[i][j] = 0.0f;

    for (int k0 = 0; k0 < K; k0 += BK) {
        // Load A tile (transposed into As[k][m]), relu-on-load optional
        int row = rowBase + am;
        float4 av = make_float4(0.f, 0.f, 0.f, 0.f);
        if (row < N)
            av = *reinterpret_cast<const float4*>(A + (size_t)row * K + k0 + ak);
        if (RELU_A) {
            av.x = fmaxf(av.x, 0.f); av.y = fmaxf(av.y, 0.f);
            av.z = fmaxf(av.z, 0.f); av.w = fmaxf(av.w, 0.f);
        }
        As[ak + 0][am] = av.x;
        As[ak + 1][am] = av.y;
        As[ak + 2][am] = av.z;
        As[ak + 3][am] = av.w;

        // Load W tile (straight copy, coalesced)
        float4 wv = *reinterpret_cast<const float4*>(
            W + (size_t)(k0 + wk) * F + colBase + wn);
        *reinterpret_cast<float4*>(&Ws[wk][wn]) = wv;

        __syncthreads();

#pragma unroll
        for (int k = 0; k < BK; k++) {
            float a[TM];
#pragma unroll
            for (int i = 0; i < TM; i++) a[i] = As[k][ty * TM + i];
            float4 bv = *reinterpret_cast<const float4*>(&Ws[k][tx * TN]);
            float b[TN] = {bv.x, bv.y, bv.z, bv.w};
#pragma unroll
            for (int i = 0; i < TM; i++)
#pragma unroll
                for (int j = 0; j < TN; j++) acc[i][j] = fmaf(a[i], b[j], acc[i][j]);
        }
        __syncthreads();
    }

    // Epilogue: write H and Agg = H*idg + bias (float4 stores)
    const int col = colBase + tx * TN;
    float4 bv = *reinterpret_cast<const float4*>(bias + col);
#pragma unroll
    for (int i = 0; i < TM; i++) {
        int row = rowBase + ty * TM + i;
        if (row >= N) continue;
        float idg = g_idg[row];
        float4 h = make_float4(acc[i][0], acc[i][1], acc[i][2], acc[i][3]);
        float4 g = make_float4(fmaf(h.x, idg, bv.x), fmaf(h.y, idg, bv.y),
                               fmaf(h.z, idg, bv.z), fmaf(h.w, idg, bv.w));
        *reinterpret_cast<float4*>(Hout + (size_t)row * F + col) = h;
        *reinterpret_cast<float4*>(Agg + (size_t)row * F + col) = g;
    }
}

// ---------------------------------------------------------------------------
// Edge scatter: one warp per edge.
//   agg[dst] += h[src] * (isd[src]*isd[dst])
// F=128 -> 4 floats/lane (float4 gather), F=64 -> 2 floats/lane (float2).
// ---------------------------------------------------------------------------
template <int F>
__global__ void __launch_bounds__(256)
k_scatter(const float* __restrict__ h, const int* __restrict__ src,
          const int* __restrict__ dst, float* __restrict__ agg, int E) {
    int gw = (blockIdx.x * blockDim.x + threadIdx.x) >> 5;
    int lane = threadIdx.x & 31;
    if (gw >= E) return;
    int s = src[gw];
    int d = dst[gw];
    float norm = g_isd[s] * g_isd[d];

    constexpr int V = F / 32;  // floats per lane
    const float* hp = h + (size_t)s * F + lane * V;
    float* ap = agg + (size_t)d * F + lane * V;

    if (V == 4) {
        float4 v = *reinterpret_cast<const float4*>(hp);
        atomicAdd(ap + 0, v.x * norm);
        atomicAdd(ap + 1, v.y * norm);
        atomicAdd(ap + 2, v.z * norm);
        atomicAdd(ap + 3, v.w * norm);
    } else {
        float2 v = *reinterpret_cast<const float2*>(hp);
        atomicAdd(ap + 0, v.x * norm);
        atomicAdd(ap + 1, v.y * norm);
    }
}

// ---------------------------------------------------------------------------
// Launch
// ---------------------------------------------------------------------------
extern "C" void kernel_launch(void* const* d_in, const int* in_sizes, int n_in,
                              void* d_out, int out_size) {
    const float* x   = (const float*)d_in[0];
    const int* eidx  = (const int*)d_in[1];
    const float* W1  = (const float*)d_in[2];
    const float* b1  = (const float*)d_in[3];
    const float* W2  = (const float*)d_in[4];
    const float* b2  = (const float*)d_in[5];
    float* out = (float*)d_out;

    const int N = in_sizes[0] / FIN;   // 50000
    const int E = in_sizes[1] / 2;     // 800000
    const int* src = eidx;             // edge_index[0, :]
    const int* dst = eidx + E;         // edge_index[1, :]

    float *h1, *agg1, *h2;
    cudaGetSymbolAddress((void**)&h1, g_h1);
    cudaGetSymbolAddress((void**)&agg1, g_agg1);
    cudaGetSymbolAddress((void**)&h2, g_h2);

    // Degrees
    k_init_deg<<<(N + 255) / 256, 256>>>(N);
    k_edge_deg<<<(E + 255) / 256, 256>>>(dst, E);
    k_finalize_deg<<<(N + 255) / 256, 256>>>(N);

    const int rowBlocks = (N + 63) / 64;

    // Layer 1: h1 = x @ W1; agg1 = h1/deg + b1
    {
        dim3 grid(FH / 64, rowBlocks);
        k_gemm_epi<FH, false><<<grid, 256>>>(x, W1, b1, h1, agg1, N);
    }
    // agg1 += scatter(h1)
    {
        int warpsPerBlock = 8;
        int blocks = (E + warpsPerBlock - 1) / warpsPerBlock;
        k_scatter<FH><<<blocks, 256>>>(h1, src, dst, agg1, E);
    }
    // Layer 2: h2 = relu(agg1) @ W2; out = h2/deg + b2
    {
        dim3 grid(FOUT / 64, rowBlocks);
        k_gemm_epi<FOUT, true><<<grid, 256>>>(agg1, W2, b2, h2, out, N);
    }
    // out += scatter(h2)
    {
        int warpsPerBlock = 8;
        int blocks = (E + warpsPerBlock - 1) / warpsPerBlock;
        k_scatter<FOUT><<<blocks, 256>>>(h2, src, dst, out, E);
    }
}

// round 2
// speedup vs baseline: 2.4885x; 2.4885x over previous
#include <cuda_runtime.h>
#include <cstdint>

#define NMAX 50000
#define EMAX 800000
#define FIN  128
#define FH   128
#define FOUT 64

// ---------------- scratch (device globals; allocation-free) ----------------
__device__ int   g_cnt[NMAX];          // in-degree counts (no self-loop)
__device__ int   g_scan[NMAX];         // block-local inclusive scan
__device__ int   g_part[256];          // per-block totals
__device__ int   g_partx[256];         // exclusive scan of totals
__device__ int   g_off[NMAX + 1];      // CSR row offsets (by dst)
__device__ int   g_cur[NMAX];          // fill cursors
__device__ int   g_srcs[EMAX];         // CSR: source node per slot
__device__ float g_w[EMAX];            // CSR: edge weight isd[s]*isd[d]
__device__ float g_isd[NMAX];          // deg^-1/2
__device__ float g_idg[NMAX];          // deg^-1
__device__ float g_h1[(size_t)NMAX * FH];
__device__ float g_agg1[(size_t)NMAX * FH];
__device__ float g_h2[(size_t)NMAX * FOUT];

// ---------------------------------------------------------------------------
// CSR build pipeline
// ---------------------------------------------------------------------------
__global__ void k_zero(int n) {
    int i = blockIdx.x * blockDim.x + threadIdx.x;
    if (i < n) g_cnt[i] = 0;
}

__global__ void k_count(const int* __restrict__ dst, int e) {
    int i = blockIdx.x * blockDim.x + threadIdx.x;
    if (i < e) atomicAdd(&g_cnt[dst[i]], 1);
}

// inclusive scan within 256-elem blocks
__global__ void k_scan1(int n) {
    __shared__ int sh[256];
    int tid = threadIdx.x;
    int i = blockIdx.x * 256 + tid;
    int v = (i < n) ? g_cnt[i] : 0;
    sh[tid] = v;
    __syncthreads();
#pragma unroll
    for (int d = 1; d < 256; d <<= 1) {
        int t = (tid >= d) ? sh[tid - d] : 0;
        __syncthreads();
        sh[tid] += t;
        __syncthreads();
    }
    if (i < n) g_scan[i] = sh[tid];
    if (tid == 255) g_part[blockIdx.x] = sh[255];
}

// exclusive scan of block totals (single block; nb <= 256)
__global__ void k_scan2(int nb) {
    __shared__ int sh[256];
    int tid = threadIdx.x;
    int v = (tid < nb) ? g_part[tid] : 0;
    sh[tid] = v;
    __syncthreads();
#pragma unroll
    for (int d = 1; d < 256; d <<= 1) {
        int t = (tid >= d) ? sh[tid - d] : 0;
        __syncthreads();
        sh[tid] += t;
        __syncthreads();
    }
    if (tid < nb) g_partx[tid] = sh[tid] - v;   // exclusive
}

// finalize: offsets, cursors, degree terms
__global__ void k_scan3(int n, int e) {
    int i = blockIdx.x * blockDim.x + threadIdx.x;
    if (i < n) {
        int c = g_cnt[i];
        int excl = g_scan[i] - c + g_partx[blockIdx.x * blockDim.x / 256 + (threadIdx.x >> 8)];
        // blockDim 256 -> block index maps 1:1 to scan1 block
        excl = g_scan[i] - c + g_partx[blockIdx.x];
        g_off[i] = excl;
        g_cur[i] = excl;
        float deg = (float)c + 1.0f;
        g_isd[i] = rsqrtf(deg);
        g_idg[i] = 1.0f / deg;
    }
    if (i == 0) g_off[n] = e;
}

__global__ void k_fill(const int* __restrict__ src, const int* __restrict__ dst, int e) {
    int i = blockIdx.x * blockDim.x + threadIdx.x;
    if (i < e) {
        int s = src[i];
        int d = dst[i];
        int pos = atomicAdd(&g_cur[d], 1);
        g_srcs[pos] = s;
        g_w[pos] = g_isd[s] * g_isd[d];
    }
}

// ---------------------------------------------------------------------------
// SGEMM: Hout = (RELU_A ? relu(A) : A) @ W,  A:[N,128], W:[128,F]
// BM=128, BN=64, BK=16, 256 threads, 8x4 register tile.
// ---------------------------------------------------------------------------
template <int F, bool RELU_A>
__global__ void __launch_bounds__(256)
k_gemm(const float* __restrict__ A, const float* __restrict__ W,
       float* __restrict__ Hout, int N) {
    constexpr int K = 128, BM = 128, BN = 64, BK = 16;
    __shared__ float As[BK][BM + 4];   // +4 pad: conflict-free transposed stores
    __shared__ float Ws[BK][BN];

    const int tid = threadIdx.x;
    const int rowBase = blockIdx.y * BM;
    const int colBase = blockIdx.x * BN;
    const int ty = tid >> 4;          // 0..15 -> 8-row slab
    const int tx = tid & 15;          // 0..15 -> 4-col slab
    const int wk = tid >> 4;          // W tile: k row
    const int wn = (tid & 15) * 4;    // W tile: col quad

    float acc[8][4];
#pragma unroll
    for (int i = 0; i < 8; i++)
#pragma unroll
        for (int j = 0; j < 4; j++) acc[i][j] = 0.0f;

    for (int k0 = 0; k0 < K; k0 += BK) {
#pragma unroll
        for (int l = 0; l < 2; l++) {
            int idx = tid + l * 256;
            int row = idx >> 2;             // 0..127
            int kq = (idx & 3) * 4;         // 0,4,8,12
            int r = rowBase + row;
            float4 av = make_float4(0.f, 0.f, 0.f, 0.f);
            if (r < N)
                av = *reinterpret_cast<const float4*>(A + (size_t)r * K + k0 + kq);
            if (RELU_A) {
                av.x = fmaxf(av.x, 0.f); av.y = fmaxf(av.y, 0.f);
                av.z = fmaxf(av.z, 0.f); av.w = fmaxf(av.w, 0.f);
            }
            As[kq + 0][row] = av.x;
            As[kq + 1][row] = av.y;
            As[kq + 2][row] = av.z;
            As[kq + 3][row] = av.w;
        }
        *reinterpret_cast<float4*>(&Ws[wk][wn]) =
            *reinterpret_cast<const float4*>(W + (size_t)(k0 + wk) * F + colBase + wn);
        __syncthreads();

#pragma unroll
        for (int k = 0; k < BK; k++) {
            float4 a0 = *reinterpret_cast<const float4*>(&As[k][ty * 8]);
            float4 a1 = *reinterpret_cast<const float4*>(&As[k][ty * 8 + 4]);
            float4 bv = *reinterpret_cast<const float4*>(&Ws[k][tx * 4]);
            float a[8] = {a0.x, a0.y, a0.z, a0.w, a1.x, a1.y, a1.z, a1.w};
            float b[4] = {bv.x, bv.y, bv.z, bv.w};
#pragma unroll
            for (int i = 0; i < 8; i++)
#pragma unroll
                for (int j = 0; j < 4; j++) acc[i][j] = fmaf(a[i], b[j], acc[i][j]);
        }
        __syncthreads();
    }

    const int col = colBase + tx * 4;
#pragma unroll
    for (int i = 0; i < 8; i++) {
        int row = rowBase + ty * 8 + i;
        if (row < N)
            *reinterpret_cast<float4*>(Hout + (size_t)row * F + col) =
                make_float4(acc[i][0], acc[i][1], acc[i][2], acc[i][3]);
    }
}

// ---------------------------------------------------------------------------
// CSR gather: one warp per destination node.
//   Out[d] = sum_{e: dst=d} H[src_e] * w_e  +  H[d]*idg[d]  +  bias
// ---------------------------------------------------------------------------
template <int F>
__global__ void __launch_bounds__(256)
k_gather(const float* __restrict__ H, const float* __restrict__ bias,
         float* __restrict__ Out, int N) {
    int gw = (blockIdx.x * blockDim.x + threadIdx.x) >> 5;
    int lane = threadIdx.x & 31;
    if (gw >= N) return;
    int beg = g_off[gw];
    int end = g_off[gw + 1];

    if (F == 128) {
        float idg = g_idg[gw];
        float4 hv = *reinterpret_cast<const float4*>(H + (size_t)gw * 128 + lane * 4);
        float4 bv = *reinterpret_cast<const float4*>(bias + lane * 4);
        float4 acc = make_float4(fmaf(hv.x, idg, bv.x), fmaf(hv.y, idg, bv.y),
                                 fmaf(hv.z, idg, bv.z), fmaf(hv.w, idg, bv.w));
        int j = beg;
        for (; j + 1 < end; j += 2) {
            int s0 = g_srcs[j];     float w0 = g_w[j];
            int s1 = g_srcs[j + 1]; float w1 = g_w[j + 1];
            float4 v0 = *reinterpret_cast<const float4*>(H + (size_t)s0 * 128 + lane * 4);
            float4 v1 = *reinterpret_cast<const float4*>(H + (size_t)s1 * 128 + lane * 4);
            acc.x = fmaf(v0.x, w0, acc.x); acc.y = fmaf(v0.y, w0, acc.y);
            acc.z = fmaf(v0.z, w0, acc.z); acc.w = fmaf(v0.w, w0, acc.w);
            acc.x = fmaf(v1.x, w1, acc.x); acc.y = fmaf(v1.y, w1, acc.y);
            acc.z = fmaf(v1.z, w1, acc.z); acc.w = fmaf(v1.w, w1, acc.w);
        }
        if (j < end) {
            int s = g_srcs[j]; float w = g_w[j];
            float4 v = *reinterpret_cast<const float4*>(H + (size_t)s * 128 + lane * 4);
            acc.x = fmaf(v.x, w, acc.x); acc.y = fmaf(v.y, w, acc.y);
            acc.z = fmaf(v.z, w, acc.z); acc.w = fmaf(v.w, w, acc.w);
        }
        *reinterpret_cast<float4*>(Out + (size_t)gw * 128 + lane * 4) = acc;
    } else {
        float idg = g_idg[gw];
        float2 hv = *reinterpret_cast<const float2*>(H + (size_t)gw * 64 + lane * 2);
        float2 bv = *reinterpret_cast<const float2*>(bias + lane * 2);
        float2 acc = make_float2(fmaf(hv.x, idg, bv.x), fmaf(hv.y, idg, bv.y));
        int j = beg;
        for (; j + 1 < end; j += 2) {
            int s0 = g_srcs[j];     float w0 = g_w[j];
            int s1 = g_srcs[j + 1]; float w1 = g_w[j + 1];
            float2 v0 = *reinterpret_cast<const float2*>(H + (size_t)s0 * 64 + lane * 2);
            float2 v1 = *reinterpret_cast<const float2*>(H + (size_t)s1 * 64 + lane * 2);
            acc.x = fmaf(v0.x, w0, acc.x); acc.y = fmaf(v0.y, w0, acc.y);
            acc.x = fmaf(v1.x, w1, acc.x); acc.y = fmaf(v1.y, w1, acc.y);
        }
        if (j < end) {
            int s = g_srcs[j]; float w = g_w[j];
            float2 v = *reinterpret_cast<const float2*>(H + (size_t)s * 64 + lane * 2);
            acc.x = fmaf(v.x, w, acc.x); acc.y = fmaf(v.y, w, acc.y);
        }
        *reinterpret_cast<float2*>(Out + (size_t)gw * 64 + lane * 2) = acc;
    }
}

// ---------------------------------------------------------------------------
// Launch
// ---------------------------------------------------------------------------
extern "C" void kernel_launch(void* const* d_in, const int* in_sizes, int n_in,
                              void* d_out, int out_size) {
    const float* x  = (const float*)d_in[0];
    const int* eidx = (const int*)d_in[1];
    const float* W1 = (const float*)d_in[2];
    const float* b1 = (const float*)d_in[3];
    const float* W2 = (const float*)d_in[4];
    const float* b2 = (const float*)d_in[5];
    float* out = (float*)d_out;

    const int N = in_sizes[0] / FIN;   // 50000
    const int E = in_sizes[1] / 2;     // 800000
    const int* src = eidx;
    const int* dst = eidx + E;

    float *h1, *agg1, *h2;
    cudaGetSymbolAddress((void**)&h1, g_h1);
    cudaGetSymbolAddress((void**)&agg1, g_agg1);
    cudaGetSymbolAddress((void**)&h2, g_h2);

    const int nScanBlocks = (N + 255) / 256;

    // --- CSR build (by dst) + degree terms ---
    k_zero<<<nScanBlocks, 256>>>(N);
    k_count<<<(E + 255) / 256, 256>>>(dst, E);
    k_scan1<<<nScanBlocks, 256>>>(N);
    k_scan2<<<1, 256>>>(nScanBlocks);
    k_scan3<<<nScanBlocks, 256>>>(N, E);
    k_fill<<<(E + 255) / 256, 256>>>(src, dst, E);

    const int rowBlocks = (N + 127) / 128;
    const int gatherBlocks = (N * 32 + 255) / 256;   // warp per node

    // Layer 1
    {
        dim3 grid(FH / 64, rowBlocks);
        k_gemm<FH, false><<<grid, 256>>>(x, W1, h1, N);
    }
    k_gather<FH><<<gatherBlocks, 256>>>(h1, b1, agg1, N);

    // Layer 2
    {
        dim3 grid(FOUT / 64, rowBlocks);
        k_gemm<FOUT, true><<<grid, 256>>>(agg1, W2, h2, N);
    }
    k_gather<FOUT><<<gatherBlocks, 256>>>(h2, b2, out, N);
}